// round 3
// baseline (speedup 1.0000x reference)
#include <cuda_runtime.h>
#include <cstdint>

// Problem constants (from reference)
#define NROW0 50
#define NROW1 50
#define NROW2 50
#define NPAIR (NROW0 * NROW1)       // 2500 (d0,d1) combos
#define TROW  512                   // t row = 16 (k) x 32 (r2) floats
#define G1LEN 4096                  // core1 row: 32*4*32
#define G0LEN 128                   // core0 row: 1*4*32
#define G2LEN 256                   // core2 row: 32*8
#define EMBD  128

// Scratch (global, allocation-free): precomputed tables
__device__ float g_t_table[NPAIR * TROW];          // [p][k*32+r], 5.12 MB (L2)
__device__ float g_core2t[NROW2 * G2LEN];          // [d2][z*32+r], 51.2 KB (L1)

// ---------------------------------------------------------------------------
// Stage 1: t_table[p] = core0[d0] (4x32) @ core1[d1] (32x128)
// Output layout: t_table[p][k*32 + s], k = x*4+y.
// ---------------------------------------------------------------------------
__global__ void __launch_bounds__(128) tt_stage1(const float* __restrict__ core0,
                                                 const float* __restrict__ core1)
{
    __shared__ float s_g1[G1LEN];
    __shared__ float s_g0[G0LEN];
    const int p   = blockIdx.x;
    const int d0  = p / NROW1;
    const int d1  = p - d0 * NROW1;
    const int tid = threadIdx.x;

    const float* g1 = core1 + (size_t)d1 * G1LEN;
    #pragma unroll
    for (int t = tid; t < G1LEN; t += 128) s_g1[t] = g1[t];
    s_g0[tid] = core0[d0 * G0LEN + tid];
    __syncthreads();

    float a0 = 0.f, a1 = 0.f, a2 = 0.f, a3 = 0.f;
    #pragma unroll
    for (int r = 0; r < 32; ++r) {
        const float g1v = s_g1[r * 128 + tid];
        a0 = fmaf(s_g0[r],      g1v, a0);
        a1 = fmaf(s_g0[32 + r], g1v, a1);
        a2 = fmaf(s_g0[64 + r], g1v, a2);
        a3 = fmaf(s_g0[96 + r], g1v, a3);
    }
    float* o = g_t_table + (size_t)p * TROW;
    o[tid]       = a0;
    o[tid + 128] = a1;
    o[tid + 256] = a2;
    o[tid + 384] = a3;
}

// ---------------------------------------------------------------------------
// Transpose core2: [d2][r*8+z] -> g_core2t[d2][z*32+r]  (12800 floats)
// ---------------------------------------------------------------------------
__global__ void __launch_bounds__(256) core2_transpose(const float* __restrict__ core2)
{
    const int u = blockIdx.x * 256 + threadIdx.x;
    if (u >= NROW2 * G2LEN) return;
    const int d2  = u >> 8;
    const int rem = u & 255;
    const int r   = rem >> 3;
    const int z   = rem & 7;
    g_core2t[(d2 << 8) + (z << 5) + r] = core2[u];
}

// ---------------------------------------------------------------------------
// Stage 2: one bag per block, 128 threads, NO shared memory.
// Thread tid owns output element e = k*8+z (k=tid>>3, z=tid&7):
//   emb[k,z] = sum_r t_table[p][k*32+r] * core2t[d2][z*32+r]
// Both operands are contiguous float4 runs -> 16 independent LDG.128/index,
// t_table L2-resident (5.12MB), core2t L1-resident (51KB).
// Cache-table bag fused (coalesced 512B row gathers, 8x unrolled).
// ---------------------------------------------------------------------------
__global__ void __launch_bounds__(128, 8) bag_kernel(
    const int*   __restrict__ indices,
    const int*   __restrict__ offsets,
    const int*   __restrict__ cached_indices,
    const int*   __restrict__ cached_offsets,
    const float* __restrict__ cache_table,
    float*       __restrict__ out,
    int num_bags)
{
    const int tid = threadIdx.x;
    const int k   = tid >> 3;
    const int z   = tid & 7;

    for (int b = blockIdx.x; b < num_bags; b += gridDim.x) {
        // ---- TT bag ----
        const int i0 = offsets[b];
        const int i1 = offsets[b + 1];
        float a0 = 0.f, a1 = 0.f, a2 = 0.f, a3 = 0.f;
        for (int i = i0; i < i1; ++i) {
            const int idx = __ldg(indices + i);      // < 125000
            const int p   = idx / 50;                // d0*50 + d1
            const int d2  = idx - p * 50;
            const float4* __restrict__ tr =
                (const float4*)(g_t_table + ((size_t)p << 9) + (k << 5));
            const float4* __restrict__ cr =
                (const float4*)(g_core2t + (d2 << 8) + (z << 5));
            float4 t0 = tr[0], t1 = tr[1], t2 = tr[2], t3 = tr[3];
            float4 t4 = tr[4], t5 = tr[5], t6 = tr[6], t7 = tr[7];
            float4 c0 = cr[0], c1 = cr[1], c2 = cr[2], c3 = cr[3];
            float4 c4 = cr[4], c5 = cr[5], c6 = cr[6], c7 = cr[7];
            a0 = fmaf(t0.x, c0.x, a0); a1 = fmaf(t0.y, c0.y, a1);
            a2 = fmaf(t0.z, c0.z, a2); a3 = fmaf(t0.w, c0.w, a3);
            a0 = fmaf(t1.x, c1.x, a0); a1 = fmaf(t1.y, c1.y, a1);
            a2 = fmaf(t1.z, c1.z, a2); a3 = fmaf(t1.w, c1.w, a3);
            a0 = fmaf(t2.x, c2.x, a0); a1 = fmaf(t2.y, c2.y, a1);
            a2 = fmaf(t2.z, c2.z, a2); a3 = fmaf(t2.w, c2.w, a3);
            a0 = fmaf(t3.x, c3.x, a0); a1 = fmaf(t3.y, c3.y, a1);
            a2 = fmaf(t3.z, c3.z, a2); a3 = fmaf(t3.w, c3.w, a3);
            a0 = fmaf(t4.x, c4.x, a0); a1 = fmaf(t4.y, c4.y, a1);
            a2 = fmaf(t4.z, c4.z, a2); a3 = fmaf(t4.w, c4.w, a3);
            a0 = fmaf(t5.x, c5.x, a0); a1 = fmaf(t5.y, c5.y, a1);
            a2 = fmaf(t5.z, c5.z, a2); a3 = fmaf(t5.w, c5.w, a3);
            a0 = fmaf(t6.x, c6.x, a0); a1 = fmaf(t6.y, c6.y, a1);
            a2 = fmaf(t6.z, c6.z, a2); a3 = fmaf(t6.w, c6.w, a3);
            a0 = fmaf(t7.x, c7.x, a0); a1 = fmaf(t7.y, c7.y, a1);
            a2 = fmaf(t7.z, c7.z, a2); a3 = fmaf(t7.w, c7.w, a3);
        }
        const float tt = (a0 + a1) + (a2 + a3);

        // ---- cached-table bag (coalesced row gather, 8x unrolled) ----
        const int j0 = cached_offsets[b];
        const int j1 = cached_offsets[b + 1];
        float cacc = 0.f;
        int j = j0;
        for (; j + 8 <= j1; j += 8) {
            float s = 0.f;
            #pragma unroll
            for (int q = 0; q < 8; ++q) {
                const int c = __ldg(cached_indices + j + q);
                s += __ldg(cache_table + (size_t)c * EMBD + tid);
            }
            cacc += s;
        }
        for (; j < j1; ++j)
            cacc += __ldg(cache_table + (size_t)__ldg(cached_indices + j) * EMBD + tid);

        out[(size_t)b * EMBD + tid] = tt + cacc;
    }
}

// ---------------------------------------------------------------------------
extern "C" void kernel_launch(void* const* d_in, const int* in_sizes, int n_in,
                              void* d_out, int out_size)
{
    const int*   indices        = (const int*)d_in[0];
    const int*   offsets        = (const int*)d_in[1];
    const int*   cached_indices = (const int*)d_in[2];
    const int*   cached_offsets = (const int*)d_in[3];
    const float* core0          = (const float*)d_in[4];
    const float* core1          = (const float*)d_in[5];
    const float* core2          = (const float*)d_in[6];
    const float* cache_table    = (const float*)d_in[7];
    float* out = (float*)d_out;

    const int num_bags = out_size / EMBD;   // 4096

    tt_stage1<<<NPAIR, 128>>>(core0, core1);
    core2_transpose<<<(NROW2 * G2LEN + 255) / 256, 256>>>(core2);

    bag_kernel<<<num_bags, 128>>>(indices, offsets, cached_indices, cached_offsets,
                                  cache_table, out, num_bags);
}

// round 4
// speedup vs baseline: 6.1511x; 6.1511x over previous
#include <cuda_runtime.h>
#include <cstdint>

// Problem constants (from reference)
#define NROW0 50
#define NROW1 50
#define NROW2 50
#define NPAIR (NROW0 * NROW1)       // 2500 (d0,d1) combos
#define TROW  512                   // t row = 16 (k) x 32 (r2) floats
#define G1LEN 4096                  // core1 row: 32*4*32
#define G0LEN 128                   // core0 row: 1*4*32
#define G2LEN 256                   // core2 row: 32*8
#define EMBD  128

// Scratch (global, allocation-free): precomputed tables
__device__ __align__(16) float g_t_table[NPAIR * TROW];   // [p][k*32+r], 5.12 MB (L2)
__device__ __align__(16) float g_core2t[NROW2 * G2LEN];   // [d2][z*32+r], 51.2 KB (L1)

// ---------------------------------------------------------------------------
// Stage 1: t_table[p] = core0[d0] (4x32) @ core1[d1] (32x128)
// Output layout: t_table[p][k*32 + s], k = x*4+y.
// ---------------------------------------------------------------------------
__global__ void __launch_bounds__(128) tt_stage1(const float* __restrict__ core0,
                                                 const float* __restrict__ core1)
{
    __shared__ float s_g1[G1LEN];
    __shared__ float s_g0[G0LEN];
    const int p   = blockIdx.x;
    const int d0  = p / NROW1;
    const int d1  = p - d0 * NROW1;
    const int tid = threadIdx.x;

    const float* g1 = core1 + (size_t)d1 * G1LEN;
    #pragma unroll
    for (int t = tid; t < G1LEN; t += 128) s_g1[t] = g1[t];
    s_g0[tid] = core0[d0 * G0LEN + tid];
    __syncthreads();

    float a0 = 0.f, a1 = 0.f, a2 = 0.f, a3 = 0.f;
    #pragma unroll
    for (int r = 0; r < 32; ++r) {
        const float g1v = s_g1[r * 128 + tid];
        a0 = fmaf(s_g0[r],      g1v, a0);
        a1 = fmaf(s_g0[32 + r], g1v, a1);
        a2 = fmaf(s_g0[64 + r], g1v, a2);
        a3 = fmaf(s_g0[96 + r], g1v, a3);
    }
    float* o = g_t_table + (size_t)p * TROW;
    o[tid]       = a0;
    o[tid + 128] = a1;
    o[tid + 256] = a2;
    o[tid + 384] = a3;
}

// ---------------------------------------------------------------------------
// Transpose core2: [d2][r*8+z] -> g_core2t[d2][z*32+r]  (12800 floats)
// ---------------------------------------------------------------------------
__global__ void __launch_bounds__(256) core2_transpose(const float* __restrict__ core2)
{
    const int u = blockIdx.x * 256 + threadIdx.x;
    if (u >= NROW2 * G2LEN) return;
    const int d2  = u >> 8;
    const int rem = u & 255;
    const int r   = rem >> 3;
    const int z   = rem & 7;
    g_core2t[(d2 << 8) + (z << 5) + r] = core2[u];
}

// ---------------------------------------------------------------------------
// Stage 2: one bag per block, 128 threads, no smem.
// Thread mapping: k = tid>>3 (output k-group), c = tid&7 (r-chunk, r=c*4..c*4+3).
// Per index: thread loads ONE t float4  (t[p][k*32 + c*4]  == float4 #(p*128+tid),
//            warp-wide 512B fully-contiguous = packed wavefronts)
// and 8 c2t float4 (one per z, 128B contiguous lines), accumulating
//   partial[z] += dot4(t_chunk, c2t[d2][z*32 + c*4 .. +3]).
// Bag end: elementwise shfl_xor reduce over the 8 chunk-lanes of each k-group;
// lane writes output z == c, i.e. element k*8+c == tid.
// Cache-table bag fused (coalesced 512B row gathers).
// ---------------------------------------------------------------------------
__global__ void __launch_bounds__(128, 6) bag_kernel(
    const int*   __restrict__ indices,
    const int*   __restrict__ offsets,
    const int*   __restrict__ cached_indices,
    const int*   __restrict__ cached_offsets,
    const float* __restrict__ cache_table,
    float*       __restrict__ out,
    int num_bags)
{
    const int tid = threadIdx.x;
    const int c8  = tid & 7;

    for (int b = blockIdx.x; b < num_bags; b += gridDim.x) {
        // ---- TT bag ----
        const int i0 = __ldg(offsets + b);
        const int i1 = __ldg(offsets + b + 1);
        float p0 = 0.f, p1 = 0.f, p2 = 0.f, p3 = 0.f;
        float p4 = 0.f, p5 = 0.f, p6 = 0.f, p7 = 0.f;

        for (int i = i0; i < i1; ++i) {
            const int idx = __ldg(indices + i);        // < 125000
            const int pq  = idx / 50;                  // d0*50 + d1 (p)
            const int d2  = idx - pq * 50;

            const float4 tv =
                __ldg((const float4*)g_t_table + pq * 128 + tid);
            const float4* __restrict__ cr =
                (const float4*)g_core2t + (d2 << 6) + c8;   // d2*64 + c8

            const float4 c0 = __ldg(cr);
            const float4 c1 = __ldg(cr + 8);
            const float4 c2 = __ldg(cr + 16);
            const float4 c3 = __ldg(cr + 24);
            const float4 c4 = __ldg(cr + 32);
            const float4 c5 = __ldg(cr + 40);
            const float4 c6 = __ldg(cr + 48);
            const float4 c7 = __ldg(cr + 56);

            p0 = fmaf(tv.x, c0.x, p0); p0 = fmaf(tv.y, c0.y, p0);
            p0 = fmaf(tv.z, c0.z, p0); p0 = fmaf(tv.w, c0.w, p0);
            p1 = fmaf(tv.x, c1.x, p1); p1 = fmaf(tv.y, c1.y, p1);
            p1 = fmaf(tv.z, c1.z, p1); p1 = fmaf(tv.w, c1.w, p1);
            p2 = fmaf(tv.x, c2.x, p2); p2 = fmaf(tv.y, c2.y, p2);
            p2 = fmaf(tv.z, c2.z, p2); p2 = fmaf(tv.w, c2.w, p2);
            p3 = fmaf(tv.x, c3.x, p3); p3 = fmaf(tv.y, c3.y, p3);
            p3 = fmaf(tv.z, c3.z, p3); p3 = fmaf(tv.w, c3.w, p3);
            p4 = fmaf(tv.x, c4.x, p4); p4 = fmaf(tv.y, c4.y, p4);
            p4 = fmaf(tv.z, c4.z, p4); p4 = fmaf(tv.w, c4.w, p4);
            p5 = fmaf(tv.x, c5.x, p5); p5 = fmaf(tv.y, c5.y, p5);
            p5 = fmaf(tv.z, c5.z, p5); p5 = fmaf(tv.w, c5.w, p5);
            p6 = fmaf(tv.x, c6.x, p6); p6 = fmaf(tv.y, c6.y, p6);
            p6 = fmaf(tv.z, c6.z, p6); p6 = fmaf(tv.w, c6.w, p6);
            p7 = fmaf(tv.x, c7.x, p7); p7 = fmaf(tv.y, c7.y, p7);
            p7 = fmaf(tv.z, c7.z, p7); p7 = fmaf(tv.w, c7.w, p7);
        }

        // Reduce partials across the 8 chunk-lanes of each k-group (lanes
        // tid&~7 .. tid|7). xor offsets 1,2,4 stay inside the 8-lane group.
        #pragma unroll
        for (int off = 1; off < 8; off <<= 1) {
            p0 += __shfl_xor_sync(0xffffffffu, p0, off);
            p1 += __shfl_xor_sync(0xffffffffu, p1, off);
            p2 += __shfl_xor_sync(0xffffffffu, p2, off);
            p3 += __shfl_xor_sync(0xffffffffu, p3, off);
            p4 += __shfl_xor_sync(0xffffffffu, p4, off);
            p5 += __shfl_xor_sync(0xffffffffu, p5, off);
            p6 += __shfl_xor_sync(0xffffffffu, p6, off);
            p7 += __shfl_xor_sync(0xffffffffu, p7, off);
        }
        float tt;
        switch (c8) {
            case 0: tt = p0; break;
            case 1: tt = p1; break;
            case 2: tt = p2; break;
            case 3: tt = p3; break;
            case 4: tt = p4; break;
            case 5: tt = p5; break;
            case 6: tt = p6; break;
            default: tt = p7; break;
        }

        // ---- cached-table bag (coalesced row gather, 4x unrolled) ----
        const int j0 = __ldg(cached_offsets + b);
        const int j1 = __ldg(cached_offsets + b + 1);
        float cacc = 0.f;
        int j = j0;
        for (; j + 4 <= j1; j += 4) {
            const int q0 = __ldg(cached_indices + j);
            const int q1 = __ldg(cached_indices + j + 1);
            const int q2 = __ldg(cached_indices + j + 2);
            const int q3 = __ldg(cached_indices + j + 3);
            const float v0 = __ldg(cache_table + (size_t)q0 * EMBD + tid);
            const float v1 = __ldg(cache_table + (size_t)q1 * EMBD + tid);
            const float v2 = __ldg(cache_table + (size_t)q2 * EMBD + tid);
            const float v3 = __ldg(cache_table + (size_t)q3 * EMBD + tid);
            cacc += (v0 + v1) + (v2 + v3);
        }
        for (; j < j1; ++j)
            cacc += __ldg(cache_table + (size_t)__ldg(cached_indices + j) * EMBD + tid);

        out[(size_t)b * EMBD + tid] = tt + cacc;
    }
}

// ---------------------------------------------------------------------------
extern "C" void kernel_launch(void* const* d_in, const int* in_sizes, int n_in,
                              void* d_out, int out_size)
{
    const int*   indices        = (const int*)d_in[0];
    const int*   offsets        = (const int*)d_in[1];
    const int*   cached_indices = (const int*)d_in[2];
    const int*   cached_offsets = (const int*)d_in[3];
    const float* core0          = (const float*)d_in[4];
    const float* core1          = (const float*)d_in[5];
    const float* core2          = (const float*)d_in[6];
    const float* cache_table    = (const float*)d_in[7];
    float* out = (float*)d_out;

    const int num_bags = out_size / EMBD;   // 4096

    tt_stage1<<<NPAIR, 128>>>(core0, core1);
    core2_transpose<<<(NROW2 * G2LEN + 255) / 256, 256>>>(core2);

    bag_kernel<<<num_bags, 128>>>(indices, offsets, cached_indices, cached_offsets,
                                  cache_table, out, num_bags);
}

// round 5
// speedup vs baseline: 9.7202x; 1.5802x over previous
#include <cuda_runtime.h>
#include <cstdint>

// Problem constants (from reference)
#define NROW0 50
#define NROW1 50
#define NROW2 50
#define NPAIR (NROW0 * NROW1)       // 2500 (d0,d1) combos
#define TROW  512                   // t row = 16 (k) x 32 (r2) floats
#define G1LEN 4096                  // core1 row: 32*4*32
#define G0LEN 128                   // core0 row: 1*4*32
#define G2LEN 256                   // core2 row: 32*8
#define EMBD  128

// Scratch (global, allocation-free): precomputed tables
__device__ __align__(16) float g_t_table[NPAIR * TROW];   // [p][k*32+r], 5.12 MB (L2)
__device__ __align__(16) float g_core2t[NROW2 * G2LEN];   // [d2][z*32+r], 51.2 KB (L1)

// ---------------------------------------------------------------------------
// Stage 1: t_table[p] = core0[d0] (4x32) @ core1[d1] (32x128)
// Output layout: t_table[p][k*32 + s], k = x*4+y.
// ---------------------------------------------------------------------------
__global__ void __launch_bounds__(128) tt_stage1(const float* __restrict__ core0,
                                                 const float* __restrict__ core1)
{
    __shared__ float s_g1[G1LEN];
    __shared__ float s_g0[G0LEN];
    const int p   = blockIdx.x;
    const int d0  = p / NROW1;
    const int d1  = p - d0 * NROW1;
    const int tid = threadIdx.x;

    const float* g1 = core1 + (size_t)d1 * G1LEN;
    #pragma unroll
    for (int t = tid; t < G1LEN; t += 128) s_g1[t] = g1[t];
    s_g0[tid] = core0[d0 * G0LEN + tid];
    __syncthreads();

    float a0 = 0.f, a1 = 0.f, a2 = 0.f, a3 = 0.f;
    #pragma unroll
    for (int r = 0; r < 32; ++r) {
        const float g1v = s_g1[r * 128 + tid];
        a0 = fmaf(s_g0[r],      g1v, a0);
        a1 = fmaf(s_g0[32 + r], g1v, a1);
        a2 = fmaf(s_g0[64 + r], g1v, a2);
        a3 = fmaf(s_g0[96 + r], g1v, a3);
    }
    float* o = g_t_table + (size_t)p * TROW;
    o[tid]       = a0;
    o[tid + 128] = a1;
    o[tid + 256] = a2;
    o[tid + 384] = a3;
}

// ---------------------------------------------------------------------------
// Transpose core2: [d2][r*8+z] -> g_core2t[d2][z*32+r]  (12800 floats)
// ---------------------------------------------------------------------------
__global__ void __launch_bounds__(256) core2_transpose(const float* __restrict__ core2)
{
    const int u = blockIdx.x * 256 + threadIdx.x;
    if (u >= NROW2 * G2LEN) return;
    const int d2  = u >> 8;
    const int rem = u & 255;
    const int r   = rem >> 3;
    const int z   = rem & 7;
    g_core2t[(d2 << 8) + (z << 5) + r] = core2[u];
}

// ---------------------------------------------------------------------------
// Stage 2: one bag per block; each INDEX handled by ONE warp (warps split the
// bag's indices 4-way).  Lane (q=lane>>3, c=lane&7):
//   - loads 4 t float4:  t[p] float4 #((q*4+m)*8 + c), m=0..3  (full 2KB row
//     covered exactly once per warp)
//   - loads 8 c2t float4: c2t[d2] float4 #(z*8 + c), z=0..7    (1KB per warp)
//   - acc[m][z] += dot4  -> 4x8 register tile, 128 FMA/index/warp
// Bag end: xor-shfl reduce over the 8 c-lanes of each q-group, lane keeps
// z==c -> 4 finals at elements q*32+m*8+c; cross-warp combine via smem[4][128].
// Cache-table bag fused (coalesced 512B row gathers by all 128 threads).
// ---------------------------------------------------------------------------
__global__ void __launch_bounds__(128, 4) bag_kernel(
    const int*   __restrict__ indices,
    const int*   __restrict__ offsets,
    const int*   __restrict__ cached_indices,
    const int*   __restrict__ cached_offsets,
    const float* __restrict__ cache_table,
    float*       __restrict__ out,
    int num_bags)
{
    __shared__ float s_part[4][EMBD];
    const int tid  = threadIdx.x;
    const int w    = tid >> 5;       // warp id 0..3
    const int lane = tid & 31;
    const int q    = lane >> 3;      // 0..3
    const int c8   = lane & 7;       // r-chunk 0..7

    for (int b = blockIdx.x; b < num_bags; b += gridDim.x) {
        // ---- TT bag: warp w takes indices i0+w, i0+w+4, ... ----
        const int i0 = __ldg(offsets + b);
        const int i1 = __ldg(offsets + b + 1);

        float acc[4][8];
        #pragma unroll
        for (int m = 0; m < 4; ++m)
            #pragma unroll
            for (int z = 0; z < 8; ++z) acc[m][z] = 0.f;

        for (int i = i0 + w; i < i1; i += 4) {
            const int idx = __ldg(indices + i);        // uniform per warp
            const int pq  = idx / 50;                  // p = d0*50+d1
            const int d2  = idx - pq * 50;

            const float4* __restrict__ tr =
                (const float4*)g_t_table + pq * 128 + q * 32 + c8;
            const float4* __restrict__ cr =
                (const float4*)g_core2t + (d2 << 6) + c8;

            float4 t0 = __ldg(tr);        // m=0  (k=q*4)
            float4 t1 = __ldg(tr + 8);    // m=1
            float4 t2 = __ldg(tr + 16);   // m=2
            float4 t3 = __ldg(tr + 24);   // m=3

            float4 cz[8];
            #pragma unroll
            for (int z = 0; z < 8; ++z) cz[z] = __ldg(cr + z * 8);

            #pragma unroll
            for (int z = 0; z < 8; ++z) {
                acc[0][z] = fmaf(t0.x, cz[z].x, acc[0][z]);
                acc[0][z] = fmaf(t0.y, cz[z].y, acc[0][z]);
                acc[0][z] = fmaf(t0.z, cz[z].z, acc[0][z]);
                acc[0][z] = fmaf(t0.w, cz[z].w, acc[0][z]);
                acc[1][z] = fmaf(t1.x, cz[z].x, acc[1][z]);
                acc[1][z] = fmaf(t1.y, cz[z].y, acc[1][z]);
                acc[1][z] = fmaf(t1.z, cz[z].z, acc[1][z]);
                acc[1][z] = fmaf(t1.w, cz[z].w, acc[1][z]);
                acc[2][z] = fmaf(t2.x, cz[z].x, acc[2][z]);
                acc[2][z] = fmaf(t2.y, cz[z].y, acc[2][z]);
                acc[2][z] = fmaf(t2.z, cz[z].z, acc[2][z]);
                acc[2][z] = fmaf(t2.w, cz[z].w, acc[2][z]);
                acc[3][z] = fmaf(t3.x, cz[z].x, acc[3][z]);
                acc[3][z] = fmaf(t3.y, cz[z].y, acc[3][z]);
                acc[3][z] = fmaf(t3.z, cz[z].z, acc[3][z]);
                acc[3][z] = fmaf(t3.w, cz[z].w, acc[3][z]);
            }
        }

        // Reduce each acc[m][z] across the 8 c-lanes of this q-group.
        #pragma unroll
        for (int off = 1; off < 8; off <<= 1)
            #pragma unroll
            for (int m = 0; m < 4; ++m)
                #pragma unroll
                for (int z = 0; z < 8; ++z)
                    acc[m][z] += __shfl_xor_sync(0xffffffffu, acc[m][z], off);

        // Lane keeps z == c8 (all 8 lanes of the group now hold identical data).
        float v0, v1, v2, v3;
        switch (c8) {
            case 0: v0=acc[0][0]; v1=acc[1][0]; v2=acc[2][0]; v3=acc[3][0]; break;
            case 1: v0=acc[0][1]; v1=acc[1][1]; v2=acc[2][1]; v3=acc[3][1]; break;
            case 2: v0=acc[0][2]; v1=acc[1][2]; v2=acc[2][2]; v3=acc[3][2]; break;
            case 3: v0=acc[0][3]; v1=acc[1][3]; v2=acc[2][3]; v3=acc[3][3]; break;
            case 4: v0=acc[0][4]; v1=acc[1][4]; v2=acc[2][4]; v3=acc[3][4]; break;
            case 5: v0=acc[0][5]; v1=acc[1][5]; v2=acc[2][5]; v3=acc[3][5]; break;
            case 6: v0=acc[0][6]; v1=acc[1][6]; v2=acc[2][6]; v3=acc[3][6]; break;
            default:v0=acc[0][7]; v1=acc[1][7]; v2=acc[2][7]; v3=acc[3][7]; break;
        }
        // element e = q*32 + m*8 + c8
        const int e0 = q * 32 + c8;
        s_part[w][e0]      = v0;
        s_part[w][e0 + 8]  = v1;
        s_part[w][e0 + 16] = v2;
        s_part[w][e0 + 24] = v3;
        __syncthreads();

        const float tt = s_part[0][tid] + s_part[1][tid]
                       + s_part[2][tid] + s_part[3][tid];

        // ---- cached-table bag (coalesced row gather, 4x unrolled) ----
        const int j0 = __ldg(cached_offsets + b);
        const int j1 = __ldg(cached_offsets + b + 1);
        float cacc = 0.f;
        int j = j0;
        for (; j + 4 <= j1; j += 4) {
            const int a0i = __ldg(cached_indices + j);
            const int a1i = __ldg(cached_indices + j + 1);
            const int a2i = __ldg(cached_indices + j + 2);
            const int a3i = __ldg(cached_indices + j + 3);
            const float f0 = __ldg(cache_table + (size_t)a0i * EMBD + tid);
            const float f1 = __ldg(cache_table + (size_t)a1i * EMBD + tid);
            const float f2 = __ldg(cache_table + (size_t)a2i * EMBD + tid);
            const float f3 = __ldg(cache_table + (size_t)a3i * EMBD + tid);
            cacc += (f0 + f1) + (f2 + f3);
        }
        for (; j < j1; ++j)
            cacc += __ldg(cache_table + (size_t)__ldg(cached_indices + j) * EMBD + tid);

        out[(size_t)b * EMBD + tid] = tt + cacc;
        __syncthreads();   // s_part reused next bag iteration (grid-stride safety)
    }
}

// ---------------------------------------------------------------------------
extern "C" void kernel_launch(void* const* d_in, const int* in_sizes, int n_in,
                              void* d_out, int out_size)
{
    const int*   indices        = (const int*)d_in[0];
    const int*   offsets        = (const int*)d_in[1];
    const int*   cached_indices = (const int*)d_in[2];
    const int*   cached_offsets = (const int*)d_in[3];
    const float* core0          = (const float*)d_in[4];
    const float* core1          = (const float*)d_in[5];
    const float* core2          = (const float*)d_in[6];
    const float* cache_table    = (const float*)d_in[7];
    float* out = (float*)d_out;

    const int num_bags = out_size / EMBD;   // 4096

    tt_stage1<<<NPAIR, 128>>>(core0, core1);
    core2_transpose<<<(NROW2 * G2LEN + 255) / 256, 256>>>(core2);

    bag_kernel<<<num_bags, 128>>>(indices, offsets, cached_indices, cached_offsets,
                                  cache_table, out, num_bags);
}